// round 13
// baseline (speedup 1.0000x reference)
#include <cuda_runtime.h>
#include <cuda_bf16.h>
#include <cstdint>

#define BB 16
#define QQ 300
#define SNUM 16
#define HID 256
#define T_TOT 13125
#define W0 100
#define H0 100
#define QP 3
#define S_SCALE_C 0.077f
#define RB 2
#define NBLK1 (BB * QP * SNUM / RB)   // 384
#define NW1 ((HID / 2) * HID)         // 32768 packed pairs
#define CVT_PER_BLK ((NW1 + NBLK1 - 1) / NBLK1)   // 86

// scratch: pre-scaled tanh offsets for the 768 distinct (b, q', s) rows
__device__ __align__(16) float g_off[BB * QP * SNUM * 4];
// w1 packed as bf16x2: w1b[c2*HID + o] = (bf16(w1[2c2][o]), bf16(w1[2c2+1][o]))
__device__ __align__(16) uint32_t w1b[NW1];   // 128KB
__device__ unsigned g_cnt;                    // cumulative ticket counter

typedef unsigned long long ull;

__device__ __forceinline__ ull pack2(float lo, float hi) {
    ull r; asm("mov.b64 %0, {%1, %2};" : "=l"(r) : "f"(lo), "f"(hi)); return r;
}
__device__ __forceinline__ void unpack2(ull v, float& lo, float& hi) {
    asm("mov.b64 {%0, %1}, %2;" : "=f"(lo), "=f"(hi) : "l"(v));
}
__device__ __forceinline__ void fma2(ull& d, ull a, ull b) {
    asm("fma.rn.f32x2 %0, %1, %2, %3;" : "=l"(d) : "l"(a), "l"(b), "l"(d));
}
__device__ __forceinline__ float tanh_fast(float x) {
    float r; asm("tanh.approx.f32 %0, %1;" : "=f"(r) : "f"(x)); return r;
}
__device__ __forceinline__ unsigned ld_cg_u32(const unsigned* p) {
    unsigned v; asm volatile("ld.global.cg.u32 %0, [%1];" : "=r"(v) : "l"(p)); return v;
}

__device__ __forceinline__ void poly_xy(const float* __restrict__ c, int s,
                                        float& spx, float& spy) {
    const float t  = (float)s * (1.0f / (float)(SNUM - 1));
    const float t2 = t * t, t3 = t2 * t;
    spx = 2.0f * (c[0] * t3 + c[1] * t2 + c[2] * t + c[3] - 0.5f);
    spy = 2.0f * (c[4] * t3 + c[5] * t2 + c[6] * t + c[7] - 0.5f);
}

// Kernel 1: convert w1 slice -> barrier (hidden behind gather) -> bf16 MLP head.
__global__ __launch_bounds__(HID, 3) void sample_mlp_kernel(
        const float* __restrict__ rp,
        const float* __restrict__ mem,
        const float* __restrict__ w1,
        const float* __restrict__ b1,
        const float* __restrict__ w2,
        const float* __restrict__ b2) {
    const int blk = blockIdx.x;
    const int tid = threadIdx.x;

    __shared__ __align__(8) float gs[HID * RB];   // [c][r]
    __shared__ float h1s[RB * HID];               // [r][o]
    __shared__ unsigned sh_tgt;

    // ---- phase 0: convert this block's slice of w1 -> w1b (bf16x2) ----
    {
        const int base = blk * CVT_PER_BLK;
        if (tid < CVT_PER_BLK) {
            const int i = base + tid;
            if (i < NW1) {
                const int o  = i & (HID - 1);
                const int c2 = i >> 8;
                const float a = __ldg(&w1[(size_t)(2 * c2) * HID + o]);
                const float b = __ldg(&w1[(size_t)(2 * c2 + 1) * HID + o]);
                const __nv_bfloat162 h = __floats2bfloat162_rn(a, b);
                w1b[i] = *reinterpret_cast<const uint32_t*>(&h);
            }
        }
    }
    __threadfence();
    __syncthreads();
    if (tid == 0) {
        const unsigned t = atomicAdd(&g_cnt, 1u);
        sh_tgt = t - (t % NBLK1) + NBLK1;
    }

    // ---- gather (independent of w1b -> overlaps other blocks' convert) ----
    #pragma unroll
    for (int it = 0; it < RB; it++) {
        const int e = it * HID + tid;
        const int c = e & (HID - 1);
        const int r = e >> 8;                  // 0..1
        const int row = blk * RB + r;          // b*48 + qp*16 + s
        const int s  = row & 15;
        const int qp = (row >> 4) % QP;
        const int b  = row / (QP * SNUM);

        float gx, gy;
        poly_xy(rp + ((size_t)b * QQ + qp) * 8, s, gx, gy);
        const float x = (gx + 1.0f) * (W0 * 0.5f) - 0.5f;
        const float y = (gy + 1.0f) * (H0 * 0.5f) - 0.5f;
        const float x0f = floorf(x), y0f = floorf(y);
        const int x0 = (int)x0f, y0 = (int)y0f;
        const float wx1 = x - x0f, wx0 = 1.0f - wx1;
        const float wy1 = y - y0f, wy0 = 1.0f - wy1;

        const float* memb = mem + (size_t)b * T_TOT * HID + c;
        float a = 0.0f;
        #pragma unroll
        for (int dy = 0; dy < 2; dy++) {
            const int yi = y0 + dy;
            if (yi < 0 || yi >= H0) continue;
            const float wy = dy ? wy1 : wy0;
            #pragma unroll
            for (int dx = 0; dx < 2; dx++) {
                const int xi = x0 + dx;
                if (xi < 0 || xi >= W0) continue;
                a += wy * (dx ? wx1 : wx0) *
                     __ldg(memb + (size_t)(yi * W0 + xi) * HID);
            }
        }
        gs[c * RB + r] = a;
    }

    // ---- barrier: wait for all conversions (mostly elapsed already) ----
    __syncthreads();
    if (tid == 0) {
        const unsigned tgt = sh_tgt;
        while ((int)(ld_cg_u32(&g_cnt) - tgt) < 0)
            __nanosleep(32);
    }
    __syncthreads();
    __threadfence();                           // acquire

    // ---- layer 1: thread = output o; bf16x2 pairs, 2 f32x2 chains ----
    // NOTE: plain loads (not __ldg) — w1b written this kernel; L1 flushed per
    // launch so post-barrier reads are correct and get free L1 reuse.
    {
        const float bv = __ldg(&b1[tid]);
        ull acc_e = pack2(bv, bv), acc_o = pack2(0.f, 0.f);
        const uint32_t* wb = w1b + tid;
        #pragma unroll 8
        for (int c2 = 0; c2 < HID / 2; c2++) {
            const uint32_t pw = wb[c2 * HID];
            const float2 wf = __bfloat1622float2(
                *reinterpret_cast<const __nv_bfloat162*>(&pw));
            fma2(acc_e, *reinterpret_cast<const ull*>(&gs[(2 * c2) * RB]),
                 pack2(wf.x, wf.x));
            fma2(acc_o, *reinterpret_cast<const ull*>(&gs[(2 * c2 + 1) * RB]),
                 pack2(wf.y, wf.y));
        }
        float e0, e1, o0, o1;
        unpack2(acc_e, e0, e1);
        unpack2(acc_o, o0, o1);
        h1s[0 * HID + tid] = tanh_fast(e0 + o0);
        h1s[1 * HID + tid] = tanh_fast(e1 + o1);
    }
    __syncthreads();

    // ---- layer 2: 8 warps = 2 rows x 4 outputs ----
    {
        const int wid = tid >> 5, lane = tid & 31;
        const int p = wid >> 2, k = wid & 3;
        float a = 0.0f;
        #pragma unroll
        for (int j = lane; j < HID; j += 32)
            a += h1s[p * HID + j] * __ldg(&w2[j * 4 + k]);
        #pragma unroll
        for (int o = 16; o > 0; o >>= 1)
            a += __shfl_xor_sync(0xffffffffu, a, o);
        if (lane == 0)
            g_off[(blk * RB + p) * 4 + k] = S_SCALE_C * tanh_fast(a + __ldg(&b2[k]));
    }
}

// Kernel 2: per (b,q,s) evaluate the cubic, gather scratch offsets by ref_level.
__global__ void out_kernel(const float* __restrict__ rp,
                           const int* __restrict__ rl,
                           float* __restrict__ out) {
    int idx = blockIdx.x * blockDim.x + threadIdx.x;   // b*Q*S + q*S + s
    if (idx >= BB * QQ * SNUM) return;
    int s = idx % SNUM;
    int q = (idx / SNUM) % QQ;
    int b = idx / (SNUM * QQ);

    const float* rpq = rp + ((size_t)b * QQ + q) * 8;
    float t  = (float)s * (1.0f / (float)(SNUM - 1));
    float t2 = t * t, t3 = t2 * t;
    float spx = 2.0f * (rpq[0] * t3 + rpq[1] * t2 + rpq[2] * t + rpq[3] - 0.5f);
    float spy = 2.0f * (rpq[4] * t3 + rpq[5] * t2 + rpq[6] * t + rpq[7] - 0.5f);

    int lvl = rl[b * QQ + q];                           // in {0,1,2}
    const float* off = g_off + (((size_t)b * QP + lvl) * SNUM + s) * 4;
    float4 v;
    v.x = off[0] + spx;
    v.y = off[1] + spy;
    v.z = off[2] + spx;
    v.w = off[3] + spy;
    reinterpret_cast<float4*>(out)[idx] = v;
}

extern "C" void kernel_launch(void* const* d_in, const int* in_sizes, int n_in,
                              void* d_out, int out_size) {
    const float* ref_polys = (const float*)d_in[0];
    const float* memory    = (const float*)d_in[1];
    const float* w1        = (const float*)d_in[2];
    const float* b1        = (const float*)d_in[3];
    const float* w2        = (const float*)d_in[4];
    const float* b2        = (const float*)d_in[5];
    const int*   ref_lvls  = (const int*)d_in[6];
    float* out = (float*)d_out;

    sample_mlp_kernel<<<NBLK1, HID>>>(ref_polys, memory, w1, b1, w2, b2);

    int total = BB * QQ * SNUM;
    out_kernel<<<(total + 255) / 256, 256>>>(ref_polys, ref_lvls, out);
}

// round 14
// speedup vs baseline: 1.0539x; 1.0539x over previous
#include <cuda_runtime.h>

#define BB 16
#define QQ 300
#define SNUM 16
#define HID 256
#define T_TOT 13125
#define W0 100
#define H0 100
#define QP 3
#define S_SCALE_C 0.077f
#define RB 6
#define GSTRIDE 8                     // padded row stride for gs / pool
#define NBLK1 (BB * QP * SNUM / RB)   // 128
#define NTHR 512
#define CH 128                        // c-half

// scratch: pre-scaled tanh offsets for the 768 distinct (b, q', s) rows
__device__ __align__(16) float g_off[BB * QP * SNUM * 4];

typedef unsigned long long ull;

__device__ __forceinline__ ull pack2(float lo, float hi) {
    ull r; asm("mov.b64 %0, {%1, %2};" : "=l"(r) : "f"(lo), "f"(hi)); return r;
}
__device__ __forceinline__ void unpack2(ull v, float& lo, float& hi) {
    asm("mov.b64 {%0, %1}, %2;" : "=f"(lo), "=f"(hi) : "l"(v));
}
__device__ __forceinline__ void fma2(ull& d, ull a, ull b) {
    asm("fma.rn.f32x2 %0, %1, %2, %3;" : "=l"(d) : "l"(a), "l"(b), "l"(d));
}
__device__ __forceinline__ float tanh_fast(float x) {
    float r; asm("tanh.approx.f32 %0, %1;" : "=f"(r) : "f"(x)); return r;
}

__device__ __forceinline__ void poly_xy(const float* __restrict__ c, int s,
                                        float& spx, float& spy) {
    const float t  = (float)s * (1.0f / (float)(SNUM - 1));
    const float t2 = t * t, t3 = t2 * t;
    spx = 2.0f * (c[0] * t3 + c[1] * t2 + c[2] * t + c[3] - 0.5f);
    spy = 2.0f * (c[4] * t3 + c[5] * t2 + c[6] * t + c[7] - 0.5f);
}

// Kernel 1: 6 rows per block, 512 threads, fp32 w1 with 2-way c-split.
// 128 blocks <= 148 SMs: one block per SM, 16 warps, no stragglers.
__global__ __launch_bounds__(NTHR, 1) void sample_mlp_kernel(
        const float* __restrict__ rp,
        const float* __restrict__ mem,
        const float* __restrict__ w1,
        const float* __restrict__ b1,
        const float* __restrict__ w2,
        const float* __restrict__ b2) {
    const int blk = blockIdx.x;
    const int tid = threadIdx.x;

    __shared__ __align__(16) float gs[HID * GSTRIDE];        // [c][r] padded, 8KB
    __shared__ __align__(16) float pool[2 * HID * GSTRIDE];  // partials, 16KB
    __shared__ float h1s[RB * HID];                          // [r][o], 6KB

    // ---- gather: 1536 (c,r) entries, 3 per thread ----
    #pragma unroll
    for (int it = 0; it < RB * HID / NTHR; it++) {   // 3
        const int e = it * NTHR + tid;
        const int c = e & (HID - 1);
        const int r = e >> 8;                  // 0..5
        const int row = blk * RB + r;          // b*48 + qp*16 + s
        const int s  = row & 15;
        const int qp = (row >> 4) % QP;
        const int b  = row / (QP * SNUM);

        float gx, gy;
        poly_xy(rp + ((size_t)b * QQ + qp) * 8, s, gx, gy);
        const float x = (gx + 1.0f) * (W0 * 0.5f) - 0.5f;
        const float y = (gy + 1.0f) * (H0 * 0.5f) - 0.5f;
        const float x0f = floorf(x), y0f = floorf(y);
        const int x0 = (int)x0f, y0 = (int)y0f;
        const float wx1 = x - x0f, wx0 = 1.0f - wx1;
        const float wy1 = y - y0f, wy0 = 1.0f - wy1;

        const float* memb = mem + (size_t)b * T_TOT * HID + c;
        float a = 0.0f;
        #pragma unroll
        for (int dy = 0; dy < 2; dy++) {
            const int yi = y0 + dy;
            if (yi < 0 || yi >= H0) continue;
            const float wy = dy ? wy1 : wy0;
            #pragma unroll
            for (int dx = 0; dx < 2; dx++) {
                const int xi = x0 + dx;
                if (xi < 0 || xi >= W0) continue;
                a += wy * (dx ? wx1 : wx0) *
                     __ldg(memb + (size_t)(yi * W0 + xi) * HID);
            }
        }
        gs[c * GSTRIDE + r] = a;
    }
    __syncthreads();

    // ---- layer 1: thread = (output o, c-half); 3 f32x2 chains = 6 rows ----
    {
        const int o  = tid & (HID - 1);
        const int ch = tid >> 8;               // 0 or 1
        ull a0 = 0, a1 = 0, a2 = 0;
        const float* wc = w1 + (size_t)(ch * CH) * HID + o;
        const float* gb = &gs[(ch * CH) * GSTRIDE];
        #pragma unroll 8
        for (int c = 0; c < CH; c++) {
            const float w = __ldg(wc + (size_t)c * HID);
            const ull wp = pack2(w, w);
            const float* g = gb + c * GSTRIDE;
            fma2(a0, *reinterpret_cast<const ull*>(g + 0), wp);
            fma2(a1, *reinterpret_cast<const ull*>(g + 2), wp);
            fma2(a2, *reinterpret_cast<const ull*>(g + 4), wp);
        }
        float* dst = &pool[(ch * HID + o) * GSTRIDE];
        float v0, v1;
        unpack2(a0, v0, v1); dst[0] = v0; dst[1] = v1;
        unpack2(a1, v0, v1); dst[2] = v0; dst[3] = v1;
        unpack2(a2, v0, v1); dst[4] = v0; dst[5] = v1;
    }
    __syncthreads();

    // ---- combine halves + bias + tanh -> h1s[r][o] ----
    if (tid < HID) {
        const float bv = __ldg(&b1[tid]);
        const float* p0 = &pool[tid * GSTRIDE];
        const float* p1 = &pool[(HID + tid) * GSTRIDE];
        #pragma unroll
        for (int r = 0; r < RB; r++)
            h1s[r * HID + tid] = tanh_fast(p0[r] + p1[r] + bv);
    }
    __syncthreads();

    // ---- layer 2: warps 0..5 -> row = wid, 4 outputs via float4 w2 rows ----
    if (tid < RB * 32) {
        const int wid = tid >> 5, lane = tid & 31;
        float a0 = 0.f, a1 = 0.f, a2 = 0.f, a3 = 0.f;
        const float4* w2v = reinterpret_cast<const float4*>(w2);
        #pragma unroll
        for (int j = lane; j < HID; j += 32) {
            const float h = h1s[wid * HID + j];
            const float4 wr = __ldg(&w2v[j]);
            a0 += h * wr.x; a1 += h * wr.y; a2 += h * wr.z; a3 += h * wr.w;
        }
        #pragma unroll
        for (int o = 16; o > 0; o >>= 1) {
            a0 += __shfl_xor_sync(0xffffffffu, a0, o);
            a1 += __shfl_xor_sync(0xffffffffu, a1, o);
            a2 += __shfl_xor_sync(0xffffffffu, a2, o);
            a3 += __shfl_xor_sync(0xffffffffu, a3, o);
        }
        if (lane == 0) {
            const float4 bb = __ldg(reinterpret_cast<const float4*>(b2));
            float4 ov;
            ov.x = S_SCALE_C * tanh_fast(a0 + bb.x);
            ov.y = S_SCALE_C * tanh_fast(a1 + bb.y);
            ov.z = S_SCALE_C * tanh_fast(a2 + bb.z);
            ov.w = S_SCALE_C * tanh_fast(a3 + bb.w);
            reinterpret_cast<float4*>(g_off)[blk * RB + wid] = ov;
        }
    }
}

// Kernel 2: per (b,q,s) evaluate the cubic, gather scratch offsets by ref_level.
// (R1 version verbatim — every "improvement" regressed it.)
__global__ void out_kernel(const float* __restrict__ rp,
                           const int* __restrict__ rl,
                           float* __restrict__ out) {
    int idx = blockIdx.x * blockDim.x + threadIdx.x;   // b*Q*S + q*S + s
    if (idx >= BB * QQ * SNUM) return;
    int s = idx % SNUM;
    int q = (idx / SNUM) % QQ;
    int b = idx / (SNUM * QQ);

    const float* rpq = rp + ((size_t)b * QQ + q) * 8;
    float t  = (float)s * (1.0f / (float)(SNUM - 1));
    float t2 = t * t, t3 = t2 * t;
    float spx = 2.0f * (rpq[0] * t3 + rpq[1] * t2 + rpq[2] * t + rpq[3] - 0.5f);
    float spy = 2.0f * (rpq[4] * t3 + rpq[5] * t2 + rpq[6] * t + rpq[7] - 0.5f);

    int lvl = rl[b * QQ + q];                           // in {0,1,2}
    const float* off = g_off + (((size_t)b * QP + lvl) * SNUM + s) * 4;
    float4 v;
    v.x = off[0] + spx;
    v.y = off[1] + spy;
    v.z = off[2] + spx;
    v.w = off[3] + spy;
    reinterpret_cast<float4*>(out)[idx] = v;
}

extern "C" void kernel_launch(void* const* d_in, const int* in_sizes, int n_in,
                              void* d_out, int out_size) {
    const float* ref_polys = (const float*)d_in[0];
    const float* memory    = (const float*)d_in[1];
    const float* w1        = (const float*)d_in[2];
    const float* b1        = (const float*)d_in[3];
    const float* w2        = (const float*)d_in[4];
    const float* b2        = (const float*)d_in[5];
    const int*   ref_lvls  = (const int*)d_in[6];
    float* out = (float*)d_out;

    sample_mlp_kernel<<<NBLK1, NTHR>>>(ref_polys, memory, w1, b1, w2, b2);

    int total = BB * QQ * SNUM;
    out_kernel<<<(total + 255) / 256, 256>>>(ref_polys, ref_lvls, out);
}